// round 1
// baseline (speedup 1.0000x reference)
#include <cuda_runtime.h>

// Problem constants
#define Bv 2
#define Sv 2048
#define Dv 768
#define Hv 12
#define HDv 64
#define Mv (Bv * Sv)   // 4096

// Scratch (device globals: allocation-free rule)
__device__ float g_qh[Bv * Hv * Sv * HDv];
__device__ float g_kh[Bv * Hv * Sv * HDv];
__device__ float g_vh[Bv * Hv * Sv * HDv];
__device__ float g_ctx[Bv * Sv * Dv];

// ---------------------------------------------------------------------------
// SGEMM: C[M,N] = A[M,K] @ W[K,N] + bias[N]
// BM=BN=128, BK=8, 256 threads, 8x8 per thread.
// HEADSPLIT: store into [B,H,S,HD] layout instead of [M,N].
// ---------------------------------------------------------------------------
template <bool HEADSPLIT>
__global__ __launch_bounds__(256) void gemm_bias_kernel(
    const float* __restrict__ A, const float* __restrict__ W,
    const float* __restrict__ bias, float* __restrict__ out,
    int M, int N, int K)
{
    __shared__ float As[8][132];  // [k][m], padded
    __shared__ float Bs[8][132];  // [k][n], padded

    const int tid  = threadIdx.x;
    const int row0 = blockIdx.y * 128;
    const int col0 = blockIdx.x * 128;

    // A tile loader: 128 rows x 8 k; 2 threads per row, float4 each
    const int arow = tid >> 1;
    const int ak   = (tid & 1) * 4;
    // B tile loader: 8 rows x 128 cols; 32 threads per row, float4 each
    const int brow = tid >> 5;
    const int bcol = (tid & 31) * 4;

    const int tx = tid & 15;  // 0..15 -> 8 output cols each
    const int ty = tid >> 4;  // 0..15 -> 8 output rows each

    float acc[8][8];
#pragma unroll
    for (int i = 0; i < 8; i++)
#pragma unroll
        for (int j = 0; j < 8; j++) acc[i][j] = 0.f;

    for (int k0 = 0; k0 < K; k0 += 8) {
        float4 av = *(const float4*)(A + (size_t)(row0 + arow) * K + k0 + ak);
        As[ak + 0][arow] = av.x;
        As[ak + 1][arow] = av.y;
        As[ak + 2][arow] = av.z;
        As[ak + 3][arow] = av.w;
        float4 bv = *(const float4*)(W + (size_t)(k0 + brow) * N + col0 + bcol);
        *(float4*)&Bs[brow][bcol] = bv;
        __syncthreads();

#pragma unroll
        for (int kk = 0; kk < 8; kk++) {
            float4 a0 = *(const float4*)&As[kk][ty * 8];
            float4 a1 = *(const float4*)&As[kk][ty * 8 + 4];
            float4 b0 = *(const float4*)&Bs[kk][tx * 8];
            float4 b1 = *(const float4*)&Bs[kk][tx * 8 + 4];
            float ar[8] = {a0.x, a0.y, a0.z, a0.w, a1.x, a1.y, a1.z, a1.w};
            float br[8] = {b0.x, b0.y, b0.z, b0.w, b1.x, b1.y, b1.z, b1.w};
#pragma unroll
            for (int i = 0; i < 8; i++)
#pragma unroll
                for (int j = 0; j < 8; j++) acc[i][j] += ar[i] * br[j];
        }
        __syncthreads();
    }

#pragma unroll
    for (int i = 0; i < 8; i++) {
        const int m = row0 + ty * 8 + i;
#pragma unroll
        for (int j = 0; j < 8; j++) {
            const int n = col0 + tx * 8 + j;
            const float v = acc[i][j] + bias[n];
            if (HEADSPLIT) {
                const int bb = m >> 11;     // m / S  (S=2048)
                const int s  = m & 2047;
                const int hh = n >> 6;      // n / HD (HD=64)
                const int hd = n & 63;
                out[(((size_t)(bb * Hv + hh) * Sv) + s) * HDv + hd] = v;
            } else {
                out[(size_t)m * N + n] = v;
            }
        }
    }
}

// ---------------------------------------------------------------------------
// Causal flash attention, fp32.
// Grid: (S/64, B*H). Block: 256 threads.
// Per block: 64 query rows; iterate key tiles of 32 up to the diagonal.
// smem: Q^T [d][i], K^T [d][j], V [j][d], scores transposed S^T [j][i].
// ---------------------------------------------------------------------------
__global__ __launch_bounds__(256) void attn_causal_kernel(
    const float* __restrict__ qh, const float* __restrict__ kh,
    const float* __restrict__ vh, float* __restrict__ ctx)
{
    __shared__ float sQ[64][68];   // [d][i], pre-scaled by 1/8
    __shared__ float sK[64][34];   // [d][j]
    __shared__ float sV[32][68];   // [j][d]
    __shared__ float sS[32][68];   // [j][i] (transposed scores -> float4 P reads)
    __shared__ float sMrow[64], sLrow[64], sAl[64];

    const int tid = threadIdx.x;
    const int qt  = blockIdx.x;   // query tile (0..31)
    const int bh  = blockIdx.y;   // 0..23
    const int b   = bh / Hv;
    const int h   = bh % Hv;

    const float* qbase = qh + ((size_t)bh * Sv + qt * 64) * 64;
    const float* kbase = kh + (size_t)bh * Sv * 64;
    const float* vbase = vh + (size_t)bh * Sv * 64;

    // Load Q tile (64x64), transposed + pre-scaled
    {
        const int r  = tid >> 2;          // 0..63
        const int c0 = (tid & 3) * 16;
        const float* src = qbase + r * 64 + c0;
#pragma unroll
        for (int u = 0; u < 16; u++) sQ[c0 + u][r] = src[u] * 0.125f;
    }
    if (tid < 64) { sMrow[tid] = -1e30f; sLrow[tid] = 0.f; }

    const int tx = tid & 15;   // 4 d-columns each
    const int ty = tid >> 4;   // 4 query rows each

    float o[4][4];
#pragma unroll
    for (int i = 0; i < 4; i++)
#pragma unroll
        for (int j = 0; j < 4; j++) o[i][j] = 0.f;

    const int ntiles = 2 * qt + 2;
    for (int jt = 0; jt < ntiles; jt++) {
        __syncthreads();
        // Load K,V tiles (32 rows x 64)
        {
            const int r  = tid >> 3;          // 0..31
            const int c0 = (tid & 7) * 8;
            const float* ks = kbase + ((size_t)jt * 32 + r) * 64 + c0;
#pragma unroll
            for (int u = 0; u < 8; u++) sK[c0 + u][r] = ks[u];
            const float* vs = vbase + ((size_t)jt * 32 + r) * 64 + c0;
            float4 v0 = *(const float4*)(vs);
            float4 v1 = *(const float4*)(vs + 4);
            *(float4*)&sV[r][c0]     = v0;
            *(float4*)&sV[r][c0 + 4] = v1;
        }
        __syncthreads();

        // Scores: per thread 4 rows x 2 cols
        float sc[4][2];
#pragma unroll
        for (int i = 0; i < 4; i++) { sc[i][0] = 0.f; sc[i][1] = 0.f; }
#pragma unroll 16
        for (int d = 0; d < 64; d++) {
            float4 a  = *(const float4*)&sQ[d][ty * 4];
            float2 kv = *(const float2*)&sK[d][tx * 2];
            sc[0][0] += a.x * kv.x;  sc[0][1] += a.x * kv.y;
            sc[1][0] += a.y * kv.x;  sc[1][1] += a.y * kv.y;
            sc[2][0] += a.z * kv.x;  sc[2][1] += a.z * kv.y;
            sc[3][0] += a.w * kv.x;  sc[3][1] += a.w * kv.y;
        }

        // Causal mask (only diagonal tiles can trigger)
        if (jt >= 2 * qt) {
#pragma unroll
            for (int i = 0; i < 4; i++)
#pragma unroll
                for (int j = 0; j < 2; j++) {
                    const int ig = qt * 64 + ty * 4 + i;
                    const int jg = jt * 32 + tx * 2 + j;
                    if (jg > ig) sc[i][j] = -1e30f;
                }
        }

        // Write transposed scores
#pragma unroll
        for (int i = 0; i < 4; i++)
#pragma unroll
            for (int j = 0; j < 2; j++)
                sS[tx * 2 + j][ty * 4 + i] = sc[i][j];
        __syncthreads();

        // Online softmax: thread group of 4 per row (aligned to lane quads)
        {
            const int r    = tid >> 2;
            const int part = tid & 3;
            float vals[8];
            float mx = -1e30f;
#pragma unroll
            for (int u = 0; u < 8; u++) {
                vals[u] = sS[part * 8 + u][r];
                mx = fmaxf(mx, vals[u]);
            }
            mx = fmaxf(mx, __shfl_xor_sync(0xffffffffu, mx, 1));
            mx = fmaxf(mx, __shfl_xor_sync(0xffffffffu, mx, 2));
            const float mold = sMrow[r];
            const float mnew = fmaxf(mold, mx);
            const float al   = __expf(mold - mnew);
            float ps = 0.f;
#pragma unroll
            for (int u = 0; u < 8; u++) {
                const float p = __expf(vals[u] - mnew);
                sS[part * 8 + u][r] = p;
                ps += p;
            }
            ps += __shfl_xor_sync(0xffffffffu, ps, 1);
            ps += __shfl_xor_sync(0xffffffffu, ps, 2);
            if (part == 0) {
                sMrow[r] = mnew;
                sLrow[r] = sLrow[r] * al + ps;
                sAl[r]   = al;
            }
        }
        __syncthreads();

        // Rescale accumulator + P@V
        float alv[4];
#pragma unroll
        for (int i = 0; i < 4; i++) alv[i] = sAl[ty * 4 + i];
#pragma unroll
        for (int i = 0; i < 4; i++)
#pragma unroll
            for (int d2 = 0; d2 < 4; d2++) o[i][d2] *= alv[i];

#pragma unroll 8
        for (int j = 0; j < 32; j++) {
            float4 p = *(const float4*)&sS[j][ty * 4];  // rows ty*4..+3 (broadcast over tx)
            float4 v = *(const float4*)&sV[j][tx * 4];
            o[0][0] += p.x * v.x;  o[0][1] += p.x * v.y;  o[0][2] += p.x * v.z;  o[0][3] += p.x * v.w;
            o[1][0] += p.y * v.x;  o[1][1] += p.y * v.y;  o[1][2] += p.y * v.z;  o[1][3] += p.y * v.w;
            o[2][0] += p.z * v.x;  o[2][1] += p.z * v.y;  o[2][2] += p.z * v.z;  o[2][3] += p.z * v.w;
            o[3][0] += p.w * v.x;  o[3][1] += p.w * v.y;  o[3][2] += p.w * v.z;  o[3][3] += p.w * v.w;
        }
    }

    // Epilogue: normalize and write ctx[B,S,D] with D-index h*64 + d
    float* obase = ctx + ((size_t)(b * Sv + qt * 64)) * Dv + h * 64;
#pragma unroll
    for (int i = 0; i < 4; i++) {
        const int r = ty * 4 + i;
        const float linv = 1.f / sLrow[r];
        float4 w = make_float4(o[i][0] * linv, o[i][1] * linv,
                               o[i][2] * linv, o[i][3] * linv);
        *(float4*)&obase[(size_t)r * Dv + tx * 4] = w;
    }
}

// ---------------------------------------------------------------------------
extern "C" void kernel_launch(void* const* d_in, const int* in_sizes, int n_in,
                              void* d_out, int out_size)
{
    const float* q  = (const float*)d_in[0];
    const float* k  = (const float*)d_in[1];
    const float* v  = (const float*)d_in[2];
    // d_in[3] = mask (causal, implemented directly)
    const float* Wq = (const float*)d_in[4];
    const float* bq = (const float*)d_in[5];
    const float* Wk = (const float*)d_in[6];
    const float* bk = (const float*)d_in[7];
    const float* Wv = (const float*)d_in[8];
    const float* bv = (const float*)d_in[9];
    const float* Wo = (const float*)d_in[10];
    const float* bo = (const float*)d_in[11];
    float* out = (float*)d_out;

    void *p_qh, *p_kh, *p_vh, *p_ctx;
    cudaGetSymbolAddress(&p_qh, g_qh);
    cudaGetSymbolAddress(&p_kh, g_kh);
    cudaGetSymbolAddress(&p_vh, g_vh);
    cudaGetSymbolAddress(&p_ctx, g_ctx);
    float* qh  = (float*)p_qh;
    float* kh  = (float*)p_kh;
    float* vh  = (float*)p_vh;
    float* ctx = (float*)p_ctx;

    dim3 gGemm(Dv / 128, Mv / 128);  // (6, 32)
    gemm_bias_kernel<true><<<gGemm, 256>>>(q, Wq, bq, qh, Mv, Dv, Dv);
    gemm_bias_kernel<true><<<gGemm, 256>>>(k, Wk, bk, kh, Mv, Dv, Dv);
    gemm_bias_kernel<true><<<gGemm, 256>>>(v, Wv, bv, vh, Mv, Dv, Dv);

    dim3 gAttn(Sv / 64, Bv * Hv);    // (32, 24)
    attn_causal_kernel<<<gAttn, 256>>>(qh, kh, vh, ctx);

    gemm_bias_kernel<false><<<gGemm, 256>>>(ctx, Wo, bo, out, Mv, Dv, Dv);
}

// round 2
// speedup vs baseline: 1.2834x; 1.2834x over previous
#include <cuda_runtime.h>
#include <cstdint>

// Problem constants
#define Bv 2
#define Sv 2048
#define Dv 768
#define Hv 12
#define HDv 64
#define Mv (Bv * Sv)   // 4096

// Scratch (device globals: allocation-free rule)
__device__ float g_qh[Bv * Hv * Sv * HDv];
__device__ float g_kh[Bv * Hv * Sv * HDv];
__device__ float g_vh[Bv * Hv * Sv * HDv];
__device__ float g_ctx[Bv * Sv * Dv];

// ---------------------------------------------------------------------------
// tf32 helpers
// ---------------------------------------------------------------------------
__device__ __forceinline__ uint32_t f2tf32(float x) {
    uint32_t u;
    asm("cvt.rna.tf32.f32 %0, %1;" : "=r"(u) : "f"(x));
    return u;
}

__device__ __forceinline__ void mma_tf32(float* d, const uint32_t* a, const uint32_t* b) {
    asm volatile(
        "mma.sync.aligned.m16n8k8.row.col.f32.tf32.tf32.f32 "
        "{%0,%1,%2,%3},{%4,%5,%6,%7},{%8,%9},{%0,%1,%2,%3};"
        : "+f"(d[0]), "+f"(d[1]), "+f"(d[2]), "+f"(d[3])
        : "r"(a[0]), "r"(a[1]), "r"(a[2]), "r"(a[3]), "r"(b[0]), "r"(b[1]));
}

// ---------------------------------------------------------------------------
// tf32 tensor-core GEMM: C[M,N] = A[M,K] @ W[K,N] + bias[N]
// Block 128x128, 256 threads (8 warps), warp tile 64x32, K-tile 32.
// HEADSPLIT: store into [B,H,S,HD] layout instead of [M,N].
// ---------------------------------------------------------------------------
template <bool HEADSPLIT>
__global__ __launch_bounds__(256) void gemm_tf32_kernel(
    const float* __restrict__ A, const float* __restrict__ W,
    const float* __restrict__ bias, float* __restrict__ out,
    int M, int N, int K)
{
    __shared__ uint32_t As[32][132];  // [k][m], tf32 bits, padded
    __shared__ uint32_t Bs[32][132];  // [k][n], tf32 bits, padded

    const int tid  = threadIdx.x;
    const int lane = tid & 31;
    const int warp = tid >> 5;
    const int gid  = lane >> 2;   // 0..7
    const int tig  = lane & 3;    // 0..3
    const int wm   = (warp & 1) * 64;   // warp M offset within block
    const int wn   = (warp >> 1) * 32;  // warp N offset within block

    const int row0 = blockIdx.y * 128;
    const int col0 = blockIdx.x * 128;

    // gmem tile loaders
    const int arow = tid >> 1;          // 0..127
    const int acol = (tid & 1) * 16;    // 0 or 16
    const int brow = tid >> 3;          // 0..31
    const int bcol = (tid & 7) * 16;    // 0..112

    const float* Aptr = A + (size_t)(row0 + arow) * K + acol;

    float4 pa[4], pb[4];
#pragma unroll
    for (int u = 0; u < 4; u++) pa[u] = *(const float4*)(Aptr + u * 4);
    {
        const float* Wp = W + (size_t)brow * N + col0 + bcol;
#pragma unroll
        for (int u = 0; u < 4; u++) pb[u] = *(const float4*)(Wp + u * 4);
    }

    float acc[16][4];
#pragma unroll
    for (int t = 0; t < 16; t++)
#pragma unroll
        for (int j = 0; j < 4; j++) acc[t][j] = 0.f;

    const int NT = K / 32;
    for (int kt = 0; kt < NT; kt++) {
        // stage current tile into smem (convert to tf32 once per element)
#pragma unroll
        for (int u = 0; u < 4; u++) {
            As[acol + u * 4 + 0][arow] = f2tf32(pa[u].x);
            As[acol + u * 4 + 1][arow] = f2tf32(pa[u].y);
            As[acol + u * 4 + 2][arow] = f2tf32(pa[u].z);
            As[acol + u * 4 + 3][arow] = f2tf32(pa[u].w);
            uint4 t;
            t.x = f2tf32(pb[u].x); t.y = f2tf32(pb[u].y);
            t.z = f2tf32(pb[u].z); t.w = f2tf32(pb[u].w);
            *(uint4*)&Bs[brow][bcol + u * 4] = t;
        }
        __syncthreads();

        // prefetch next tile
        if (kt + 1 < NT) {
            const float* An = Aptr + (kt + 1) * 32;
            const float* Wn = W + (size_t)((kt + 1) * 32 + brow) * N + col0 + bcol;
#pragma unroll
            for (int u = 0; u < 4; u++) pa[u] = *(const float4*)(An + u * 4);
#pragma unroll
            for (int u = 0; u < 4; u++) pb[u] = *(const float4*)(Wn + u * 4);
        }

        // compute: 4 k-steps of m16n8k8
#pragma unroll
        for (int ks = 0; ks < 4; ks++) {
            const int kk = ks * 8 + tig;
            uint32_t af[4][4], bf[4][2];
#pragma unroll
            for (int mt = 0; mt < 4; mt++) {
                const int m = wm + mt * 16 + gid;
                af[mt][0] = As[kk][m];
                af[mt][1] = As[kk][m + 8];
                af[mt][2] = As[kk + 4][m];
                af[mt][3] = As[kk + 4][m + 8];
            }
#pragma unroll
            for (int nt = 0; nt < 4; nt++) {
                const int n = wn + nt * 8 + gid;
                bf[nt][0] = Bs[kk][n];
                bf[nt][1] = Bs[kk + 4][n];
            }
#pragma unroll
            for (int mt = 0; mt < 4; mt++)
#pragma unroll
                for (int nt = 0; nt < 4; nt++)
                    mma_tf32(acc[mt * 4 + nt], af[mt], bf[nt]);
        }
        __syncthreads();
    }

    // epilogue: bias + store (float2 per row pair)
#pragma unroll
    for (int mt = 0; mt < 4; mt++) {
        const int r0 = row0 + wm + mt * 16 + gid;
        const int r1 = r0 + 8;
#pragma unroll
        for (int nt = 0; nt < 4; nt++) {
            const float* d = acc[mt * 4 + nt];
            const int n = col0 + wn + nt * 8 + tig * 2;
            const float b0 = bias[n];
            const float b1 = bias[n + 1];
            float2 v0 = make_float2(d[0] + b0, d[1] + b1);
            float2 v1 = make_float2(d[2] + b0, d[3] + b1);
            if (HEADSPLIT) {
                const int hh = n >> 6;
                const int hd = n & 63;
                {
                    const int bb = r0 >> 11, s = r0 & 2047;
                    *(float2*)&out[(((size_t)(bb * Hv + hh) * Sv) + s) * HDv + hd] = v0;
                }
                {
                    const int bb = r1 >> 11, s = r1 & 2047;
                    *(float2*)&out[(((size_t)(bb * Hv + hh) * Sv) + s) * HDv + hd] = v1;
                }
            } else {
                *(float2*)&out[(size_t)r0 * N + n] = v0;
                *(float2*)&out[(size_t)r1 * N + n] = v1;
            }
        }
    }
}

// ---------------------------------------------------------------------------
// Causal flash attention, fp32 (unchanged from R1).
// ---------------------------------------------------------------------------
__global__ __launch_bounds__(256) void attn_causal_kernel(
    const float* __restrict__ qh, const float* __restrict__ kh,
    const float* __restrict__ vh, float* __restrict__ ctx)
{
    __shared__ float sQ[64][68];   // [d][i], pre-scaled by 1/8
    __shared__ float sK[64][34];   // [d][j]
    __shared__ float sV[32][68];   // [j][d]
    __shared__ float sS[32][68];   // [j][i]
    __shared__ float sMrow[64], sLrow[64], sAl[64];

    const int tid = threadIdx.x;
    const int qt  = blockIdx.x;
    const int bh  = blockIdx.y;
    const int b   = bh / Hv;
    const int h   = bh % Hv;

    const float* qbase = qh + ((size_t)bh * Sv + qt * 64) * 64;
    const float* kbase = kh + (size_t)bh * Sv * 64;
    const float* vbase = vh + (size_t)bh * Sv * 64;

    {
        const int r  = tid >> 2;
        const int c0 = (tid & 3) * 16;
        const float* src = qbase + r * 64 + c0;
#pragma unroll
        for (int u = 0; u < 16; u++) sQ[c0 + u][r] = src[u] * 0.125f;
    }
    if (tid < 64) { sMrow[tid] = -1e30f; sLrow[tid] = 0.f; }

    const int tx = tid & 15;
    const int ty = tid >> 4;

    float o[4][4];
#pragma unroll
    for (int i = 0; i < 4; i++)
#pragma unroll
        for (int j = 0; j < 4; j++) o[i][j] = 0.f;

    const int ntiles = 2 * qt + 2;
    for (int jt = 0; jt < ntiles; jt++) {
        __syncthreads();
        {
            const int r  = tid >> 3;
            const int c0 = (tid & 7) * 8;
            const float* ks = kbase + ((size_t)jt * 32 + r) * 64 + c0;
#pragma unroll
            for (int u = 0; u < 8; u++) sK[c0 + u][r] = ks[u];
            const float* vs = vbase + ((size_t)jt * 32 + r) * 64 + c0;
            float4 v0 = *(const float4*)(vs);
            float4 v1 = *(const float4*)(vs + 4);
            *(float4*)&sV[r][c0]     = v0;
            *(float4*)&sV[r][c0 + 4] = v1;
        }
        __syncthreads();

        float sc[4][2];
#pragma unroll
        for (int i = 0; i < 4; i++) { sc[i][0] = 0.f; sc[i][1] = 0.f; }
#pragma unroll 16
        for (int d = 0; d < 64; d++) {
            float4 a  = *(const float4*)&sQ[d][ty * 4];
            float2 kv = *(const float2*)&sK[d][tx * 2];
            sc[0][0] += a.x * kv.x;  sc[0][1] += a.x * kv.y;
            sc[1][0] += a.y * kv.x;  sc[1][1] += a.y * kv.y;
            sc[2][0] += a.z * kv.x;  sc[2][1] += a.z * kv.y;
            sc[3][0] += a.w * kv.x;  sc[3][1] += a.w * kv.y;
        }

        if (jt >= 2 * qt) {
#pragma unroll
            for (int i = 0; i < 4; i++)
#pragma unroll
                for (int j = 0; j < 2; j++) {
                    const int ig = qt * 64 + ty * 4 + i;
                    const int jg = jt * 32 + tx * 2 + j;
                    if (jg > ig) sc[i][j] = -1e30f;
                }
        }

#pragma unroll
        for (int i = 0; i < 4; i++)
#pragma unroll
            for (int j = 0; j < 2; j++)
                sS[tx * 2 + j][ty * 4 + i] = sc[i][j];
        __syncthreads();

        {
            const int r    = tid >> 2;
            const int part = tid & 3;
            float vals[8];
            float mx = -1e30f;
#pragma unroll
            for (int u = 0; u < 8; u++) {
                vals[u] = sS[part * 8 + u][r];
                mx = fmaxf(mx, vals[u]);
            }
            mx = fmaxf(mx, __shfl_xor_sync(0xffffffffu, mx, 1));
            mx = fmaxf(mx, __shfl_xor_sync(0xffffffffu, mx, 2));
            const float mold = sMrow[r];
            const float mnew = fmaxf(mold, mx);
            const float al   = __expf(mold - mnew);
            float ps = 0.f;
#pragma unroll
            for (int u = 0; u < 8; u++) {
                const float p = __expf(vals[u] - mnew);
                sS[part * 8 + u][r] = p;
                ps += p;
            }
            ps += __shfl_xor_sync(0xffffffffu, ps, 1);
            ps += __shfl_xor_sync(0xffffffffu, ps, 2);
            if (part == 0) {
                sMrow[r] = mnew;
                sLrow[r] = sLrow[r] * al + ps;
                sAl[r]   = al;
            }
        }
        __syncthreads();

        float alv[4];
#pragma unroll
        for (int i = 0; i < 4; i++) alv[i] = sAl[ty * 4 + i];
#pragma unroll
        for (int i = 0; i < 4; i++)
#pragma unroll
            for (int d2 = 0; d2 < 4; d2++) o[i][d2] *= alv[i];

#pragma unroll 8
        for (int j = 0; j < 32; j++) {
            float4 p = *(const float4*)&sS[j][ty * 4];
            float4 v = *(const float4*)&sV[j][tx * 4];
            o[0][0] += p.x * v.x;  o[0][1] += p.x * v.y;  o[0][2] += p.x * v.z;  o[0][3] += p.x * v.w;
            o[1][0] += p.y * v.x;  o[1][1] += p.y * v.y;  o[1][2] += p.y * v.z;  o[1][3] += p.y * v.w;
            o[2][0] += p.z * v.x;  o[2][1] += p.z * v.y;  o[2][2] += p.z * v.z;  o[2][3] += p.z * v.w;
            o[3][0] += p.w * v.x;  o[3][1] += p.w * v.y;  o[3][2] += p.w * v.z;  o[3][3] += p.w * v.w;
        }
    }

    float* obase = ctx + ((size_t)(b * Sv + qt * 64)) * Dv + h * 64;
#pragma unroll
    for (int i = 0; i < 4; i++) {
        const int r = ty * 4 + i;
        const float linv = 1.f / sLrow[r];
        float4 w = make_float4(o[i][0] * linv, o[i][1] * linv,
                               o[i][2] * linv, o[i][3] * linv);
        *(float4*)&obase[(size_t)r * Dv + tx * 4] = w;
    }
}

// ---------------------------------------------------------------------------
extern "C" void kernel_launch(void* const* d_in, const int* in_sizes, int n_in,
                              void* d_out, int out_size)
{
    const float* q  = (const float*)d_in[0];
    const float* k  = (const float*)d_in[1];
    const float* v  = (const float*)d_in[2];
    // d_in[3] = mask (causal, implemented directly)
    const float* Wq = (const float*)d_in[4];
    const float* bq = (const float*)d_in[5];
    const float* Wk = (const float*)d_in[6];
    const float* bk = (const float*)d_in[7];
    const float* Wv = (const float*)d_in[8];
    const float* bv = (const float*)d_in[9];
    const float* Wo = (const float*)d_in[10];
    const float* bo = (const float*)d_in[11];
    float* out = (float*)d_out;

    void *p_qh, *p_kh, *p_vh, *p_ctx;
    cudaGetSymbolAddress(&p_qh, g_qh);
    cudaGetSymbolAddress(&p_kh, g_kh);
    cudaGetSymbolAddress(&p_vh, g_vh);
    cudaGetSymbolAddress(&p_ctx, g_ctx);
    float* qh  = (float*)p_qh;
    float* kh  = (float*)p_kh;
    float* vh  = (float*)p_vh;
    float* ctx = (float*)p_ctx;

    dim3 gGemm(Dv / 128, Mv / 128);  // (6, 32)
    gemm_tf32_kernel<true><<<gGemm, 256>>>(q, Wq, bq, qh, Mv, Dv, Dv);
    gemm_tf32_kernel<true><<<gGemm, 256>>>(k, Wk, bk, kh, Mv, Dv, Dv);
    gemm_tf32_kernel<true><<<gGemm, 256>>>(v, Wv, bv, vh, Mv, Dv, Dv);

    dim3 gAttn(Sv / 64, Bv * Hv);    // (32, 24)
    attn_causal_kernel<<<gAttn, 256>>>(qh, kh, vh, ctx);

    gemm_tf32_kernel<false><<<gGemm, 256>>>(ctx, Wo, bo, out, Mv, Dv, Dv);
}

// round 3
// speedup vs baseline: 3.0303x; 2.3611x over previous
#include <cuda_runtime.h>
#include <cstdint>

// Problem constants
#define Bv 2
#define Sv 2048
#define Dv 768
#define Hv 12
#define HDv 64
#define Mv (Bv * Sv)   // 4096

// Scratch (device globals: allocation-free rule)
__device__ float g_qh[Bv * Hv * Sv * HDv];
__device__ float g_kh[Bv * Hv * Sv * HDv];
__device__ float g_vh[Bv * Hv * Sv * HDv];
__device__ float g_ctx[Bv * Sv * Dv];

// ---------------------------------------------------------------------------
// tf32 helpers
// ---------------------------------------------------------------------------
__device__ __forceinline__ uint32_t f2tf32(float x) {
    uint32_t u;
    asm("cvt.rna.tf32.f32 %0, %1;" : "=r"(u) : "f"(x));
    return u;
}

__device__ __forceinline__ float ex2(float x) {
    float y;
    asm("ex2.approx.ftz.f32 %0, %1;" : "=f"(y) : "f"(x));
    return y;
}

__device__ __forceinline__ void mma_tf32(float* d, const uint32_t* a, const uint32_t* b) {
    asm volatile(
        "mma.sync.aligned.m16n8k8.row.col.f32.tf32.tf32.f32 "
        "{%0,%1,%2,%3},{%4,%5,%6,%7},{%8,%9},{%0,%1,%2,%3};"
        : "+f"(d[0]), "+f"(d[1]), "+f"(d[2]), "+f"(d[3])
        : "r"(a[0]), "r"(a[1]), "r"(a[2]), "r"(a[3]), "r"(b[0]), "r"(b[1]));
}

// ---------------------------------------------------------------------------
// tf32 tensor-core GEMM body: C[M,N] = A[M,K] @ W[K,N] + bias[N]
// Block 128x128, 256 threads (8 warps), warp tile 64x32, K-tile 32.
// M = Mv, N = K = Dv fixed.
// ---------------------------------------------------------------------------
template <bool HEADSPLIT>
__device__ __forceinline__ void gemm_body(
    const float* __restrict__ A, const float* __restrict__ W,
    const float* __restrict__ bias, float* __restrict__ out)
{
    const int M = Mv, N = Dv, K = Dv;
    __shared__ uint32_t As[32][132];  // [k][m], tf32 bits, padded
    __shared__ uint32_t Bs[32][132];  // [k][n], tf32 bits, padded

    const int tid  = threadIdx.x;
    const int lane = tid & 31;
    const int warp = tid >> 5;
    const int gid  = lane >> 2;
    const int tig  = lane & 3;
    const int wm   = (warp & 1) * 64;
    const int wn   = (warp >> 1) * 32;

    const int row0 = blockIdx.y * 128;
    const int col0 = blockIdx.x * 128;

    const int arow = tid >> 1;
    const int acol = (tid & 1) * 16;
    const int brow = tid >> 3;
    const int bcol = (tid & 7) * 16;

    const float* Aptr = A + (size_t)(row0 + arow) * K + acol;

    float4 pa[4], pb[4];
#pragma unroll
    for (int u = 0; u < 4; u++) pa[u] = *(const float4*)(Aptr + u * 4);
    {
        const float* Wp = W + (size_t)brow * N + col0 + bcol;
#pragma unroll
        for (int u = 0; u < 4; u++) pb[u] = *(const float4*)(Wp + u * 4);
    }

    float acc[16][4];
#pragma unroll
    for (int t = 0; t < 16; t++)
#pragma unroll
        for (int j = 0; j < 4; j++) acc[t][j] = 0.f;

    const int NT = K / 32;
    for (int kt = 0; kt < NT; kt++) {
#pragma unroll
        for (int u = 0; u < 4; u++) {
            As[acol + u * 4 + 0][arow] = f2tf32(pa[u].x);
            As[acol + u * 4 + 1][arow] = f2tf32(pa[u].y);
            As[acol + u * 4 + 2][arow] = f2tf32(pa[u].z);
            As[acol + u * 4 + 3][arow] = f2tf32(pa[u].w);
            uint4 t;
            t.x = f2tf32(pb[u].x); t.y = f2tf32(pb[u].y);
            t.z = f2tf32(pb[u].z); t.w = f2tf32(pb[u].w);
            *(uint4*)&Bs[brow][bcol + u * 4] = t;
        }
        __syncthreads();

        if (kt + 1 < NT) {
            const float* An = Aptr + (kt + 1) * 32;
            const float* Wn = W + (size_t)((kt + 1) * 32 + brow) * N + col0 + bcol;
#pragma unroll
            for (int u = 0; u < 4; u++) pa[u] = *(const float4*)(An + u * 4);
#pragma unroll
            for (int u = 0; u < 4; u++) pb[u] = *(const float4*)(Wn + u * 4);
        }

#pragma unroll
        for (int ks = 0; ks < 4; ks++) {
            const int kk = ks * 8 + tig;
            uint32_t af[4][4], bf[4][2];
#pragma unroll
            for (int mt = 0; mt < 4; mt++) {
                const int m = wm + mt * 16 + gid;
                af[mt][0] = As[kk][m];
                af[mt][1] = As[kk][m + 8];
                af[mt][2] = As[kk + 4][m];
                af[mt][3] = As[kk + 4][m + 8];
            }
#pragma unroll
            for (int nt = 0; nt < 4; nt++) {
                const int n = wn + nt * 8 + gid;
                bf[nt][0] = Bs[kk][n];
                bf[nt][1] = Bs[kk + 4][n];
            }
#pragma unroll
            for (int mt = 0; mt < 4; mt++)
#pragma unroll
                for (int nt = 0; nt < 4; nt++)
                    mma_tf32(acc[mt * 4 + nt], af[mt], bf[nt]);
        }
        __syncthreads();
    }

#pragma unroll
    for (int mt = 0; mt < 4; mt++) {
        const int r0 = row0 + wm + mt * 16 + gid;
        const int r1 = r0 + 8;
#pragma unroll
        for (int nt = 0; nt < 4; nt++) {
            const float* d = acc[mt * 4 + nt];
            const int n = col0 + wn + nt * 8 + tig * 2;
            const float b0 = bias[n];
            const float b1 = bias[n + 1];
            float2 v0 = make_float2(d[0] + b0, d[1] + b1);
            float2 v1 = make_float2(d[2] + b0, d[3] + b1);
            if (HEADSPLIT) {
                const int hh = n >> 6;
                const int hd = n & 63;
                {
                    const int bb = r0 >> 11, s = r0 & 2047;
                    *(float2*)&out[(((size_t)(bb * Hv + hh) * Sv) + s) * HDv + hd] = v0;
                }
                {
                    const int bb = r1 >> 11, s = r1 & 2047;
                    *(float2*)&out[(((size_t)(bb * Hv + hh) * Sv) + s) * HDv + hd] = v1;
                }
            } else {
                *(float2*)&out[(size_t)r0 * N + n] = v0;
                *(float2*)&out[(size_t)r1 * N + n] = v1;
            }
        }
    }
}

// Merged Q/K/V projection: blockIdx.z selects input/weight/bias/output.
__global__ __launch_bounds__(256) void gemm_qkv_kernel(
    const float* __restrict__ q, const float* __restrict__ k, const float* __restrict__ v,
    const float* __restrict__ Wq, const float* __restrict__ Wk, const float* __restrict__ Wv,
    const float* __restrict__ bq, const float* __restrict__ bk, const float* __restrict__ bv,
    float* __restrict__ qh, float* __restrict__ kh, float* __restrict__ vh)
{
    const int z = blockIdx.z;
    const float* A    = (z == 0) ? q  : (z == 1) ? k  : v;
    const float* W    = (z == 0) ? Wq : (z == 1) ? Wk : Wv;
    const float* bias = (z == 0) ? bq : (z == 1) ? bk : bv;
    float*       out  = (z == 0) ? qh : (z == 1) ? kh : vh;
    gemm_body<true>(A, W, bias, out);
}

__global__ __launch_bounds__(256) void gemm_out_kernel(
    const float* __restrict__ A, const float* __restrict__ W,
    const float* __restrict__ bias, float* __restrict__ out)
{
    gemm_body<false>(A, W, bias, out);
}

// ---------------------------------------------------------------------------
// tf32 tensor-core causal flash attention.
// Grid (16, B*H), 256 threads (8 warps). BM=128 q-rows (warp tile M=16),
// BN=32 keys per KV tile. Q fragments live in registers for the whole loop.
// Scores computed in log2 domain (1/8 * log2e folded into Q).
// ---------------------------------------------------------------------------
#define LOG2E 1.4426950408889634f

__global__ __launch_bounds__(256) void attn_mma_kernel(
    const float* __restrict__ qh, const float* __restrict__ kh,
    const float* __restrict__ vh, float* __restrict__ ctx)
{
    __shared__ uint32_t sK[32][68];    // [key][d]   tf32; frag bank = 4*gid+tig
    __shared__ uint32_t sV[32][76];    // [key][d]   tf32; frag bank = 12*tig+gid
    __shared__ uint32_t sP[128][36];   // [qrow][key] tf32

    const int tid  = threadIdx.x;
    const int lane = tid & 31;
    const int warp = tid >> 5;
    const int gid  = lane >> 2;
    const int tig  = lane & 3;
    const int wm   = warp * 16;

    const int qt = (gridDim.x - 1) - blockIdx.x;  // long blocks first
    const int bh = blockIdx.y;
    const int b  = bh / Hv;
    const int h  = bh % Hv;

    const float* qb = qh + ((size_t)bh * Sv + qt * 128) * 64;
    const float* kb = kh + (size_t)bh * Sv * 64;
    const float* vb = vh + (size_t)bh * Sv * 64;

    // Q fragments in registers: 8 k-steps x 4 regs (rows wm+gid, wm+gid+8)
    const float SC = 0.125f * LOG2E;
    uint32_t qa[8][4];
#pragma unroll
    for (int ks = 0; ks < 8; ks++) {
        qa[ks][0] = f2tf32(qb[(wm + gid) * 64 + ks * 8 + tig] * SC);
        qa[ks][1] = f2tf32(qb[(wm + gid + 8) * 64 + ks * 8 + tig] * SC);
        qa[ks][2] = f2tf32(qb[(wm + gid) * 64 + ks * 8 + tig + 4] * SC);
        qa[ks][3] = f2tf32(qb[(wm + gid + 8) * 64 + ks * 8 + tig + 4] * SC);
    }

    float m0 = -1e30f, m1 = -1e30f, l0 = 0.f, l1 = 0.f;
    float o[8][4];
#pragma unroll
    for (int nt = 0; nt < 8; nt++)
#pragma unroll
        for (int j = 0; j < 4; j++) o[nt][j] = 0.f;

    const int ig0 = qt * 128 + wm + gid;   // this thread's row 0 global index
    const int r_kv = tid >> 3;             // 0..31
    const int c_kv = (tid & 7) * 8;        // 0..56

    const int ntiles = 4 * qt + 4;
    for (int jt = 0; jt < ntiles; jt++) {
        __syncthreads();
        // Load K,V tile (32 keys x 64) as tf32
        {
            const float* kp = kb + ((size_t)jt * 32 + r_kv) * 64 + c_kv;
            const float* vp = vb + ((size_t)jt * 32 + r_kv) * 64 + c_kv;
            float4 k0 = *(const float4*)kp;
            float4 k1 = *(const float4*)(kp + 4);
            float4 v0 = *(const float4*)vp;
            float4 v1 = *(const float4*)(vp + 4);
            uint2 t;
            t.x = f2tf32(k0.x); t.y = f2tf32(k0.y); *(uint2*)&sK[r_kv][c_kv + 0] = t;
            t.x = f2tf32(k0.z); t.y = f2tf32(k0.w); *(uint2*)&sK[r_kv][c_kv + 2] = t;
            t.x = f2tf32(k1.x); t.y = f2tf32(k1.y); *(uint2*)&sK[r_kv][c_kv + 4] = t;
            t.x = f2tf32(k1.z); t.y = f2tf32(k1.w); *(uint2*)&sK[r_kv][c_kv + 6] = t;
            t.x = f2tf32(v0.x); t.y = f2tf32(v0.y); *(uint2*)&sV[r_kv][c_kv + 0] = t;
            t.x = f2tf32(v0.z); t.y = f2tf32(v0.w); *(uint2*)&sV[r_kv][c_kv + 2] = t;
            t.x = f2tf32(v1.x); t.y = f2tf32(v1.y); *(uint2*)&sV[r_kv][c_kv + 4] = t;
            t.x = f2tf32(v1.z); t.y = f2tf32(v1.w); *(uint2*)&sV[r_kv][c_kv + 6] = t;
        }
        __syncthreads();

        // Skip compute if this warp's 16 rows are entirely above this key tile
        if (jt * 32 > qt * 128 + wm + 15) continue;

        // ---- QK^T: scores [16 x 32] per warp ----
        float sacc[4][4];
#pragma unroll
        for (int nt = 0; nt < 4; nt++)
#pragma unroll
            for (int j = 0; j < 4; j++) sacc[nt][j] = 0.f;

#pragma unroll
        for (int ks = 0; ks < 8; ks++) {
#pragma unroll
            for (int nt = 0; nt < 4; nt++) {
                uint32_t bf[2];
                bf[0] = sK[nt * 8 + gid][ks * 8 + tig];
                bf[1] = sK[nt * 8 + gid][ks * 8 + tig + 4];
                mma_tf32(sacc[nt], qa[ks], bf);
            }
        }

        // ---- causal mask (diagonal tiles only) ----
        if (jt >= 4 * qt) {
#pragma unroll
            for (int nt = 0; nt < 4; nt++) {
                const int jg = jt * 32 + nt * 8 + 2 * tig;
                if (jg > ig0)         sacc[nt][0] = -1e30f;
                if (jg + 1 > ig0)     sacc[nt][1] = -1e30f;
                if (jg > ig0 + 8)     sacc[nt][2] = -1e30f;
                if (jg + 1 > ig0 + 8) sacc[nt][3] = -1e30f;
            }
        }

        // ---- online softmax (log2 domain) ----
        float mx0 = -1e30f, mx1 = -1e30f;
#pragma unroll
        for (int nt = 0; nt < 4; nt++) {
            mx0 = fmaxf(mx0, fmaxf(sacc[nt][0], sacc[nt][1]));
            mx1 = fmaxf(mx1, fmaxf(sacc[nt][2], sacc[nt][3]));
        }
        mx0 = fmaxf(mx0, __shfl_xor_sync(0xffffffffu, mx0, 1));
        mx0 = fmaxf(mx0, __shfl_xor_sync(0xffffffffu, mx0, 2));
        mx1 = fmaxf(mx1, __shfl_xor_sync(0xffffffffu, mx1, 1));
        mx1 = fmaxf(mx1, __shfl_xor_sync(0xffffffffu, mx1, 2));

        const float nm0 = fmaxf(m0, mx0);
        const float nm1 = fmaxf(m1, mx1);
        const float a0 = ex2(m0 - nm0);
        const float a1 = ex2(m1 - nm1);
        m0 = nm0; m1 = nm1;

        float ps0 = 0.f, ps1 = 0.f;
#pragma unroll
        for (int nt = 0; nt < 4; nt++) {
            const float p00 = ex2(sacc[nt][0] - m0);
            const float p01 = ex2(sacc[nt][1] - m0);
            const float p10 = ex2(sacc[nt][2] - m1);
            const float p11 = ex2(sacc[nt][3] - m1);
            ps0 += p00 + p01;
            ps1 += p10 + p11;
            uint2 t;
            t.x = f2tf32(p00); t.y = f2tf32(p01);
            *(uint2*)&sP[wm + gid][nt * 8 + 2 * tig] = t;
            t.x = f2tf32(p10); t.y = f2tf32(p11);
            *(uint2*)&sP[wm + gid + 8][nt * 8 + 2 * tig] = t;
        }
        ps0 += __shfl_xor_sync(0xffffffffu, ps0, 1);
        ps0 += __shfl_xor_sync(0xffffffffu, ps0, 2);
        ps1 += __shfl_xor_sync(0xffffffffu, ps1, 1);
        ps1 += __shfl_xor_sync(0xffffffffu, ps1, 2);
        l0 = l0 * a0 + ps0;
        l1 = l1 * a1 + ps1;

        // rescale accumulator
#pragma unroll
        for (int nt = 0; nt < 8; nt++) {
            o[nt][0] *= a0; o[nt][1] *= a0;
            o[nt][2] *= a1; o[nt][3] *= a1;
        }
        __syncwarp();

        // ---- P @ V ----
#pragma unroll
        for (int ks = 0; ks < 4; ks++) {
            uint32_t pa[4];
            pa[0] = sP[wm + gid][ks * 8 + tig];
            pa[1] = sP[wm + gid + 8][ks * 8 + tig];
            pa[2] = sP[wm + gid][ks * 8 + tig + 4];
            pa[3] = sP[wm + gid + 8][ks * 8 + tig + 4];
#pragma unroll
            for (int nt = 0; nt < 8; nt++) {
                uint32_t bf[2];
                bf[0] = sV[ks * 8 + tig][nt * 8 + gid];
                bf[1] = sV[ks * 8 + tig + 4][nt * 8 + gid];
                mma_tf32(o[nt], pa, bf);
            }
        }
    }

    // ---- epilogue: normalize, write ctx[b, row, h*64+d] ----
    const float il0 = 1.f / l0;
    const float il1 = 1.f / l1;
    float* ob = ctx + ((size_t)(b * Sv + qt * 128 + wm + gid)) * Dv + h * 64;
#pragma unroll
    for (int nt = 0; nt < 8; nt++) {
        const int c = nt * 8 + 2 * tig;
        *(float2*)&ob[c]            = make_float2(o[nt][0] * il0, o[nt][1] * il0);
        *(float2*)&ob[8 * Dv + c]   = make_float2(o[nt][2] * il1, o[nt][3] * il1);
    }
}

// ---------------------------------------------------------------------------
extern "C" void kernel_launch(void* const* d_in, const int* in_sizes, int n_in,
                              void* d_out, int out_size)
{
    const float* q  = (const float*)d_in[0];
    const float* k  = (const float*)d_in[1];
    const float* v  = (const float*)d_in[2];
    // d_in[3] = mask (causal, implemented directly)
    const float* Wq = (const float*)d_in[4];
    const float* bq = (const float*)d_in[5];
    const float* Wk = (const float*)d_in[6];
    const float* bk = (const float*)d_in[7];
    const float* Wv = (const float*)d_in[8];
    const float* bv = (const float*)d_in[9];
    const float* Wo = (const float*)d_in[10];
    const float* bo = (const float*)d_in[11];
    float* out = (float*)d_out;

    void *p_qh, *p_kh, *p_vh, *p_ctx;
    cudaGetSymbolAddress(&p_qh, g_qh);
    cudaGetSymbolAddress(&p_kh, g_kh);
    cudaGetSymbolAddress(&p_vh, g_vh);
    cudaGetSymbolAddress(&p_ctx, g_ctx);
    float* qh  = (float*)p_qh;
    float* kh  = (float*)p_kh;
    float* vh  = (float*)p_vh;
    float* ctx = (float*)p_ctx;

    dim3 gQKV(Dv / 128, Mv / 128, 3);  // (6, 32, 3)
    gemm_qkv_kernel<<<gQKV, 256>>>(q, k, v, Wq, Wk, Wv, bq, bk, bv, qh, kh, vh);

    dim3 gAttn(Sv / 128, Bv * Hv);     // (16, 24)
    attn_mma_kernel<<<gAttn, 256>>>(qh, kh, vh, ctx);

    dim3 gGemm(Dv / 128, Mv / 128);    // (6, 32)
    gemm_out_kernel<<<gGemm, 256>>>(ctx, Wo, bo, out);
}

// round 5
// speedup vs baseline: 4.6825x; 1.5452x over previous
#include <cuda_runtime.h>
#include <cstdint>

// Problem constants
#define Bv 2
#define Sv 2048
#define Dv 768
#define Hv 12
#define HDv 64
#define Mv (Bv * Sv)   // 4096

// Scratch (device globals: allocation-free rule)
__device__ float    g_qh[Mv * Dv];    // tf32-bit floats
__device__ float    g_kh[Mv * Dv];
__device__ float    g_vh[Mv * Dv];
__device__ float    g_ctx[Mv * Dv];   // tf32-bit floats
__device__ uint32_t g_qc[Mv * Dv];    // pre-converted tf32 inputs
__device__ uint32_t g_kc[Mv * Dv];
__device__ uint32_t g_vc[Mv * Dv];
__device__ uint32_t g_Wqc[Dv * Dv];
__device__ uint32_t g_Wkc[Dv * Dv];
__device__ uint32_t g_Wvc[Dv * Dv];
__device__ uint32_t g_Woc[Dv * Dv];

// ---------------------------------------------------------------------------
// helpers
// ---------------------------------------------------------------------------
__device__ __forceinline__ uint32_t f2tf32(float x) {
    uint32_t u;
    asm("cvt.rna.tf32.f32 %0, %1;" : "=r"(u) : "f"(x));
    return u;
}

__device__ __forceinline__ float ex2(float x) {
    float y;
    asm("ex2.approx.ftz.f32 %0, %1;" : "=f"(y) : "f"(x));
    return y;
}

__device__ __forceinline__ void mma_tf32(float* d, const uint32_t* a, const uint32_t* b) {
    asm volatile(
        "mma.sync.aligned.m16n8k8.row.col.f32.tf32.tf32.f32 "
        "{%0,%1,%2,%3},{%4,%5,%6,%7},{%8,%9},{%0,%1,%2,%3};"
        : "+f"(d[0]), "+f"(d[1]), "+f"(d[2]), "+f"(d[3])
        : "r"(a[0]), "r"(a[1]), "r"(a[2]), "r"(a[3]), "r"(b[0]), "r"(b[1]));
}

__device__ __forceinline__ void cp16(void* dst, const void* src) {
    uint32_t d = (uint32_t)__cvta_generic_to_shared(dst);
    asm volatile("cp.async.cg.shared.global [%0], [%1], 16;" :: "r"(d), "l"(src));
}
#define CP_COMMIT asm volatile("cp.async.commit_group;" ::: "memory")
#define CP_WAIT1  asm volatile("cp.async.wait_group 1;" ::: "memory")

// ---------------------------------------------------------------------------
// tf32 pre-conversion kernels
// ---------------------------------------------------------------------------
__global__ void cvt3_kernel(const float4* __restrict__ a, const float4* __restrict__ b,
                            const float4* __restrict__ c,
                            uint4* __restrict__ oa, uint4* __restrict__ ob,
                            uint4* __restrict__ oc, int n4)
{
    const int i = blockIdx.x * 256 + threadIdx.x;
    if (i >= n4) return;
    const float4* s = (blockIdx.y == 0) ? a : (blockIdx.y == 1) ? b : c;
    uint4*        d = (blockIdx.y == 0) ? oa : (blockIdx.y == 1) ? ob : oc;
    float4 v = s[i];
    uint4 o;
    o.x = f2tf32(v.x); o.y = f2tf32(v.y); o.z = f2tf32(v.z); o.w = f2tf32(v.w);
    d[i] = o;
}

__global__ void cvt4_kernel(const float4* __restrict__ a, const float4* __restrict__ b,
                            const float4* __restrict__ c, const float4* __restrict__ e,
                            uint4* __restrict__ oa, uint4* __restrict__ ob,
                            uint4* __restrict__ oc, uint4* __restrict__ oe, int n4)
{
    const int i = blockIdx.x * 256 + threadIdx.x;
    if (i >= n4) return;
    const float4* s = (blockIdx.y == 0) ? a : (blockIdx.y == 1) ? b : (blockIdx.y == 2) ? c : e;
    uint4*        d = (blockIdx.y == 0) ? oa : (blockIdx.y == 1) ? ob : (blockIdx.y == 2) ? oc : oe;
    float4 v = s[i];
    uint4 o;
    o.x = f2tf32(v.x); o.y = f2tf32(v.y); o.z = f2tf32(v.z); o.w = f2tf32(v.w);
    d[i] = o;
}

// ---------------------------------------------------------------------------
// tf32 GEMM: C[M,N] = A[M,K] @ W[K,N] + bias, inputs pre-converted tf32 bits.
// Block 128x128, 128 threads (4 warps), warp tile 64x64, K-tile 32,
// 2-stage cp.async double buffer. Dynamic smem = 70656 B.
// SPLIT_TF32: headsplit output layout + store tf32 bits.
// ---------------------------------------------------------------------------
#define GEMM_SMEM ((2 * 128 * 36 + 2 * 32 * 132) * 4)

template <bool SPLIT_TF32>
__device__ __forceinline__ void gemm_body(
    const uint32_t* __restrict__ A, const uint32_t* __restrict__ W,
    const float* __restrict__ bias, float* __restrict__ out)
{
    extern __shared__ uint32_t dsm[];
    uint32_t (*As)[128][36] = (uint32_t(*)[128][36])dsm;                 // [2][128][36]
    uint32_t (*Bs)[32][132] = (uint32_t(*)[32][132])(dsm + 2 * 128 * 36);

    const int tid  = threadIdx.x;
    const int lane = tid & 31;
    const int warp = tid >> 5;
    const int gid  = lane >> 2;
    const int tig  = lane & 3;
    const int wm   = (warp & 1) * 64;
    const int wn   = (warp >> 1) * 64;
    const int row0 = blockIdx.y * 128;
    const int col0 = blockIdx.x * 128;

    auto issue = [&](int kt, int s) {
#pragma unroll
        for (int it = 0; it < 8; it++) {
            const int c = it * 128 + tid;
            const int r = c >> 3, u = (c & 7) * 4;
            cp16(&As[s][r][u], A + (size_t)(row0 + r) * Dv + kt * 32 + u);
        }
#pragma unroll
        for (int it = 0; it < 8; it++) {
            const int c = it * 128 + tid;
            const int r = c >> 5, u = (c & 31) * 4;
            cp16(&Bs[s][r][u], W + (size_t)(kt * 32 + r) * Dv + col0 + u);
        }
    };

    float acc[4][8][4] = {};

    issue(0, 0); CP_COMMIT;
    issue(1, 1); CP_COMMIT;

    const int NT = Dv / 32;  // 24
    for (int kt = 0; kt < NT; kt++) {
        CP_WAIT1;
        __syncthreads();
        const int s = kt & 1;
#pragma unroll
        for (int ks = 0; ks < 4; ks++) {
            uint32_t af[4][4], bf[8][2];
            const int kk = ks * 8 + tig;
#pragma unroll
            for (int mt = 0; mt < 4; mt++) {
                const int m = wm + mt * 16 + gid;
                af[mt][0] = As[s][m][kk];
                af[mt][1] = As[s][m + 8][kk];
                af[mt][2] = As[s][m][kk + 4];
                af[mt][3] = As[s][m + 8][kk + 4];
            }
#pragma unroll
            for (int nt = 0; nt < 8; nt++) {
                const int n = wn + nt * 8 + gid;
                bf[nt][0] = Bs[s][kk][n];
                bf[nt][1] = Bs[s][kk + 4][n];
            }
#pragma unroll
            for (int mt = 0; mt < 4; mt++)
#pragma unroll
                for (int nt = 0; nt < 8; nt++)
                    mma_tf32(acc[mt][nt], af[mt], bf[nt]);
        }
        __syncthreads();
        if (kt + 2 < NT) issue(kt + 2, s);
        CP_COMMIT;
    }

    // epilogue
#pragma unroll
    for (int mt = 0; mt < 4; mt++) {
        const int r0 = row0 + wm + mt * 16 + gid;
        const int r1 = r0 + 8;
#pragma unroll
        for (int nt = 0; nt < 8; nt++) {
            const float* d = acc[mt][nt];
            const int n = col0 + wn + nt * 8 + 2 * tig;
            const float b0 = bias[n];
            const float b1 = bias[n + 1];
            if (SPLIT_TF32) {
                const int hh = n >> 6;
                const int hd = n & 63;
                float2 v0, v1;
                v0.x = __uint_as_float(f2tf32(d[0] + b0));
                v0.y = __uint_as_float(f2tf32(d[1] + b1));
                v1.x = __uint_as_float(f2tf32(d[2] + b0));
                v1.y = __uint_as_float(f2tf32(d[3] + b1));
                {
                    const int bb = r0 >> 11, ss = r0 & 2047;
                    *(float2*)&out[(((size_t)(bb * Hv + hh) * Sv) + ss) * HDv + hd] = v0;
                }
                {
                    const int bb = r1 >> 11, ss = r1 & 2047;
                    *(float2*)&out[(((size_t)(bb * Hv + hh) * Sv) + ss) * HDv + hd] = v1;
                }
            } else {
                *(float2*)&out[(size_t)r0 * Dv + n] = make_float2(d[0] + b0, d[1] + b1);
                *(float2*)&out[(size_t)r1 * Dv + n] = make_float2(d[2] + b0, d[3] + b1);
            }
        }
    }
}

__global__ __launch_bounds__(128) void gemm_qkv_kernel(
    const uint32_t* __restrict__ q, const uint32_t* __restrict__ k, const uint32_t* __restrict__ v,
    const uint32_t* __restrict__ Wq, const uint32_t* __restrict__ Wk, const uint32_t* __restrict__ Wv,
    const float* __restrict__ bq, const float* __restrict__ bk, const float* __restrict__ bv,
    float* __restrict__ qh, float* __restrict__ kh, float* __restrict__ vh)
{
    const int z = blockIdx.z;
    const uint32_t* A    = (z == 0) ? q  : (z == 1) ? k  : v;
    const uint32_t* W    = (z == 0) ? Wq : (z == 1) ? Wk : Wv;
    const float*    bias = (z == 0) ? bq : (z == 1) ? bk : bv;
    float*          out  = (z == 0) ? qh : (z == 1) ? kh : vh;
    gemm_body<true>(A, W, bias, out);
}

__global__ __launch_bounds__(128) void gemm_out_kernel(
    const uint32_t* __restrict__ A, const uint32_t* __restrict__ W,
    const float* __restrict__ bias, float* __restrict__ out)
{
    gemm_body<false>(A, W, bias, out);
}

// ---------------------------------------------------------------------------
// tf32 causal flash attention.
// Grid (16, B*H), 128 threads (4 warps). BM=128 (warp-M 32), BN=32.
// Q fragments in registers; K/V cp.async double-buffered; log2-domain softmax.
// Dynamic smem: sK[2][32][68], sV[2][32][76], sP[128][36] = 55296 B.
// ---------------------------------------------------------------------------
#define LOG2E 1.4426950408889634f
#define ATTN_SMEM ((2 * 32 * 68 + 2 * 32 * 76 + 128 * 36) * 4)

__global__ __launch_bounds__(128) void attn_mma_kernel(
    const float* __restrict__ qh, const float* __restrict__ kh,
    const float* __restrict__ vh, float* __restrict__ ctx)
{
    extern __shared__ uint32_t dynsm[];
    uint32_t (*sK)[32][68] = (uint32_t(*)[32][68])dynsm;                     // [2][32][68]
    uint32_t (*sV)[32][76] = (uint32_t(*)[32][76])(dynsm + 2 * 32 * 68);     // [2][32][76]
    uint32_t (*sP)[36]     = (uint32_t(*)[36])(dynsm + 2 * 32 * 68 + 2 * 32 * 76); // [128][36]

    const int tid  = threadIdx.x;
    const int lane = tid & 31;
    const int warp = tid >> 5;
    const int gid  = lane >> 2;
    const int tig  = lane & 3;
    const int wm   = warp * 32;

    const int qt = (gridDim.x - 1) - blockIdx.x;  // long blocks first
    const int bh = blockIdx.y;
    const int b  = bh / Hv;
    const int hd = bh % Hv;

    const float* qb = qh + ((size_t)bh * Sv + qt * 128) * 64;
    const float* kb = kh + (size_t)bh * Sv * 64;
    const float* vb = vh + (size_t)bh * Sv * 64;

    // Q fragments: 8 ksteps x 2 mtiles x 4 regs
    const float SC = 0.125f * LOG2E;
    uint32_t qa[8][2][4];
#pragma unroll
    for (int ks = 0; ks < 8; ks++)
#pragma unroll
        for (int mt = 0; mt < 2; mt++) {
            const int r = wm + mt * 16 + gid;
            qa[ks][mt][0] = f2tf32(qb[r * 64 + ks * 8 + tig] * SC);
            qa[ks][mt][1] = f2tf32(qb[(r + 8) * 64 + ks * 8 + tig] * SC);
            qa[ks][mt][2] = f2tf32(qb[r * 64 + ks * 8 + tig + 4] * SC);
            qa[ks][mt][3] = f2tf32(qb[(r + 8) * 64 + ks * 8 + tig + 4] * SC);
        }

    float m[2][2] = {{-1e30f, -1e30f}, {-1e30f, -1e30f}};
    float l[2][2] = {{0.f, 0.f}, {0.f, 0.f}};
    float o[2][8][4] = {};

    auto issueKV = [&](int jt, int s) {
        const float* kp = kb + (size_t)jt * 32 * 64;
        const float* vp = vb + (size_t)jt * 32 * 64;
#pragma unroll
        for (int it = 0; it < 4; it++) {
            const int c = it * 128 + tid;
            const int r = c >> 4, u = (c & 15) * 4;
            cp16(&sK[s][r][u], kp + r * 64 + u);
            cp16(&sV[s][r][u], vp + r * 64 + u);
        }
    };

    const int ntiles = 4 * qt + 4;
    issueKV(0, 0); CP_COMMIT;
    issueKV(1, 1); CP_COMMIT;

    for (int jt = 0; jt < ntiles; jt++) {
        CP_WAIT1;
        __syncthreads();
        const int s = jt & 1;

        if (jt * 32 <= qt * 128 + wm + 31) {  // warp has unmasked rows in this tile
            // ---- QK^T ----
            float sacc[2][4][4] = {};
#pragma unroll
            for (int ks = 0; ks < 8; ks++) {
                const int kk = ks * 8 + tig;
#pragma unroll
                for (int nt = 0; nt < 4; nt++) {
                    uint32_t bf[2];
                    bf[0] = sK[s][nt * 8 + gid][kk];
                    bf[1] = sK[s][nt * 8 + gid][kk + 4];
                    mma_tf32(sacc[0][nt], qa[ks][0], bf);
                    mma_tf32(sacc[1][nt], qa[ks][1], bf);
                }
            }

            // ---- causal mask (diagonal region only) ----
            if (jt >= 4 * qt) {
#pragma unroll
                for (int mt = 0; mt < 2; mt++) {
                    const int ig = qt * 128 + wm + mt * 16 + gid;
#pragma unroll
                    for (int nt = 0; nt < 4; nt++) {
                        const int jg = jt * 32 + nt * 8 + 2 * tig;
                        if (jg > ig)         sacc[mt][nt][0] = -1e30f;
                        if (jg + 1 > ig)     sacc[mt][nt][1] = -1e30f;
                        if (jg > ig + 8)     sacc[mt][nt][2] = -1e30f;
                        if (jg + 1 > ig + 8) sacc[mt][nt][3] = -1e30f;
                    }
                }
            }

            // ---- online softmax (log2 domain) ----
#pragma unroll
            for (int mt = 0; mt < 2; mt++) {
                float mx0 = -1e30f, mx1 = -1e30f;
#pragma unroll
                for (int nt = 0; nt < 4; nt++) {
                    mx0 = fmaxf(mx0, fmaxf(sacc[mt][nt][0], sacc[mt][nt][1]));
                    mx1 = fmaxf(mx1, fmaxf(sacc[mt][nt][2], sacc[mt][nt][3]));
                }
                mx0 = fmaxf(mx0, __shfl_xor_sync(0xffffffffu, mx0, 1));
                mx0 = fmaxf(mx0, __shfl_xor_sync(0xffffffffu, mx0, 2));
                mx1 = fmaxf(mx1, __shfl_xor_sync(0xffffffffu, mx1, 1));
                mx1 = fmaxf(mx1, __shfl_xor_sync(0xffffffffu, mx1, 2));

                const float nm0 = fmaxf(m[mt][0], mx0);
                const float nm1 = fmaxf(m[mt][1], mx1);
                const float a0 = ex2(m[mt][0] - nm0);
                const float a1 = ex2(m[mt][1] - nm1);
                m[mt][0] = nm0; m[mt][1] = nm1;

                const int r = wm + mt * 16 + gid;
                float ps0 = 0.f, ps1 = 0.f;
#pragma unroll
                for (int nt = 0; nt < 4; nt++) {
                    const float p00 = ex2(sacc[mt][nt][0] - nm0);
                    const float p01 = ex2(sacc[mt][nt][1] - nm0);
                    const float p10 = ex2(sacc[mt][nt][2] - nm1);
                    const float p11 = ex2(sacc[mt][nt][3] - nm1);
                    ps0 += p00 + p01;
                    ps1 += p10 + p11;
                    uint2 t;
                    t.x = f2tf32(p00); t.y = f2tf32(p01);
                    *(uint2*)&sP[r][nt * 8 + 2 * tig] = t;
                    t.x = f2tf32(p10); t.y = f2tf32(p11);
                    *(uint2*)&sP[r + 8][nt * 8 + 2 * tig] = t;
                }
                ps0 += __shfl_xor_sync(0xffffffffu, ps0, 1);
                ps0 += __shfl_xor_sync(0xffffffffu, ps0, 2);
                ps1 += __shfl_xor_sync(0xffffffffu, ps1, 1);
                ps1 += __shfl_xor_sync(0xffffffffu, ps1, 2);
                l[mt][0] = l[mt][0] * a0 + ps0;
                l[mt][1] = l[mt][1] * a1 + ps1;

#pragma unroll
                for (int nt = 0; nt < 8; nt++) {
                    o[mt][nt][0] *= a0; o[mt][nt][1] *= a0;
                    o[mt][nt][2] *= a1; o[mt][nt][3] *= a1;
                }
            }
            __syncwarp();

            // ---- P @ V ----
#pragma unroll
            for (int ks = 0; ks < 4; ks++) {
                const int kk = ks * 8 + tig;
                uint32_t pa[2][4];
#pragma unroll
                for (int mt = 0; mt < 2; mt++) {
                    const int r = wm + mt * 16 + gid;
                    pa[mt][0] = sP[r][kk];
                    pa[mt][1] = sP[r + 8][kk];
                    pa[mt][2] = sP[r][kk + 4];
                    pa[mt][3] = sP[r + 8][kk + 4];
                }
#pragma unroll
                for (int nt = 0; nt < 8; nt++) {
                    uint32_t bf[2];
                    bf[0] = sV[s][kk][nt * 8 + gid];
                    bf[1] = sV[s][kk + 4][nt * 8 + gid];
                    mma_tf32(o[0][nt], pa[0], bf);
                    mma_tf32(o[1][nt], pa[1], bf);
                }
            }
        }

        __syncthreads();
        if (jt + 2 < ntiles) issueKV(jt + 2, s);
        CP_COMMIT;
    }

    // ---- epilogue: normalize, write ctx as tf32 bits ----
#pragma unroll
    for (int mt = 0; mt < 2; mt++)
#pragma unroll
        for (int hf = 0; hf < 2; hf++) {
            const float il = 1.f / l[mt][hf];
            const int r = qt * 128 + wm + mt * 16 + gid + hf * 8;
            float* ob = ctx + ((size_t)(b * Sv + r)) * Dv + hd * 64;
#pragma unroll
            for (int nt = 0; nt < 8; nt++) {
                uint2 w;
                w.x = f2tf32(o[mt][nt][2 * hf + 0] * il);
                w.y = f2tf32(o[mt][nt][2 * hf + 1] * il);
                *(uint2*)&ob[nt * 8 + 2 * tig] = w;
            }
        }
}

// ---------------------------------------------------------------------------
extern "C" void kernel_launch(void* const* d_in, const int* in_sizes, int n_in,
                              void* d_out, int out_size)
{
    const float* q  = (const float*)d_in[0];
    const float* k  = (const float*)d_in[1];
    const float* v  = (const float*)d_in[2];
    // d_in[3] = mask (causal, implemented directly)
    const float* Wq = (const float*)d_in[4];
    const float* bq = (const float*)d_in[5];
    const float* Wk = (const float*)d_in[6];
    const float* bk = (const float*)d_in[7];
    const float* Wv = (const float*)d_in[8];
    const float* bv = (const float*)d_in[9];
    const float* Wo = (const float*)d_in[10];
    const float* bo = (const float*)d_in[11];
    float* out = (float*)d_out;

    void *p_qh, *p_kh, *p_vh, *p_ctx, *p_qc, *p_kc, *p_vc, *p_wq, *p_wk, *p_wv, *p_wo;
    cudaGetSymbolAddress(&p_qh, g_qh);
    cudaGetSymbolAddress(&p_kh, g_kh);
    cudaGetSymbolAddress(&p_vh, g_vh);
    cudaGetSymbolAddress(&p_ctx, g_ctx);
    cudaGetSymbolAddress(&p_qc, g_qc);
    cudaGetSymbolAddress(&p_kc, g_kc);
    cudaGetSymbolAddress(&p_vc, g_vc);
    cudaGetSymbolAddress(&p_wq, g_Wqc);
    cudaGetSymbolAddress(&p_wk, g_Wkc);
    cudaGetSymbolAddress(&p_wv, g_Wvc);
    cudaGetSymbolAddress(&p_wo, g_Woc);

    cudaFuncSetAttribute(gemm_qkv_kernel, cudaFuncAttributeMaxDynamicSharedMemorySize, GEMM_SMEM);
    cudaFuncSetAttribute(gemm_out_kernel, cudaFuncAttributeMaxDynamicSharedMemorySize, GEMM_SMEM);
    cudaFuncSetAttribute(attn_mma_kernel, cudaFuncAttributeMaxDynamicSharedMemorySize, ATTN_SMEM);

    // pre-convert inputs + weights to tf32 bits
    cvt3_kernel<<<dim3(Mv * Dv / 1024, 3), 256>>>(
        (const float4*)q, (const float4*)k, (const float4*)v,
        (uint4*)p_qc, (uint4*)p_kc, (uint4*)p_vc, Mv * Dv / 4);
    cvt4_kernel<<<dim3(Dv * Dv / 1024, 4), 256>>>(
        (const float4*)Wq, (const float4*)Wk, (const float4*)Wv, (const float4*)Wo,
        (uint4*)p_wq, (uint4*)p_wk, (uint4*)p_wv, (uint4*)p_wo, Dv * Dv / 4);

    dim3 gQKV(Dv / 128, Mv / 128, 3);  // (6, 32, 3)
    gemm_qkv_kernel<<<gQKV, 128, GEMM_SMEM>>>(
        (const uint32_t*)p_qc, (const uint32_t*)p_kc, (const uint32_t*)p_vc,
        (const uint32_t*)p_wq, (const uint32_t*)p_wk, (const uint32_t*)p_wv,
        bq, bk, bv, (float*)p_qh, (float*)p_kh, (float*)p_vh);

    dim3 gAttn(Sv / 128, Bv * Hv);     // (16, 24)
    attn_mma_kernel<<<gAttn, 128, ATTN_SMEM>>>((const float*)p_qh, (const float*)p_kh,
                                               (const float*)p_vh, (float*)p_ctx);

    dim3 gGemm(Dv / 128, Mv / 128);    // (6, 32)
    gemm_out_kernel<<<gGemm, 128, GEMM_SMEM>>>(
        (const uint32_t*)p_ctx, (const uint32_t*)p_wo, bo, out);
}

// round 6
// speedup vs baseline: 4.7132x; 1.0066x over previous
#include <cuda_runtime.h>
#include <cstdint>

// Problem constants
#define Bv 2
#define Sv 2048
#define Dv 768
#define Hv 12
#define HDv 64
#define Mv (Bv * Sv)   // 4096

// Scratch (device globals: allocation-free rule)
__device__ float    g_qh[Mv * Dv];    // tf32-bit floats
__device__ float    g_kh[Mv * Dv];
__device__ float    g_vh[Mv * Dv];
__device__ float    g_ctx[Mv * Dv];   // tf32-bit floats
__device__ uint32_t g_qc[Mv * Dv];    // pre-converted tf32 inputs
__device__ uint32_t g_kc[Mv * Dv];
__device__ uint32_t g_vc[Mv * Dv];
__device__ uint32_t g_Wqc[Dv * Dv];
__device__ uint32_t g_Wkc[Dv * Dv];
__device__ uint32_t g_Wvc[Dv * Dv];
__device__ uint32_t g_Woc[Dv * Dv];

// ---------------------------------------------------------------------------
// helpers
// ---------------------------------------------------------------------------
__device__ __forceinline__ uint32_t f2tf32(float x) {
    uint32_t u;
    asm("cvt.rna.tf32.f32 %0, %1;" : "=r"(u) : "f"(x));
    return u;
}

__device__ __forceinline__ float ex2(float x) {
    float y;
    asm("ex2.approx.ftz.f32 %0, %1;" : "=f"(y) : "f"(x));
    return y;
}

__device__ __forceinline__ void mma_tf32(float* d, const uint32_t* a, const uint32_t* b) {
    asm volatile(
        "mma.sync.aligned.m16n8k8.row.col.f32.tf32.tf32.f32 "
        "{%0,%1,%2,%3},{%4,%5,%6,%7},{%8,%9},{%0,%1,%2,%3};"
        : "+f"(d[0]), "+f"(d[1]), "+f"(d[2]), "+f"(d[3])
        : "r"(a[0]), "r"(a[1]), "r"(a[2]), "r"(a[3]), "r"(b[0]), "r"(b[1]));
}

__device__ __forceinline__ void cp16(void* dst, const void* src) {
    uint32_t d = (uint32_t)__cvta_generic_to_shared(dst);
    asm volatile("cp.async.cg.shared.global [%0], [%1], 16;" :: "r"(d), "l"(src));
}
#define CP_COMMIT asm volatile("cp.async.commit_group;" ::: "memory")
#define CP_WAIT1  asm volatile("cp.async.wait_group 1;" ::: "memory")

// ---------------------------------------------------------------------------
// tf32 pre-conversion kernels
// ---------------------------------------------------------------------------
__global__ void cvt3_kernel(const float4* __restrict__ a, const float4* __restrict__ b,
                            const float4* __restrict__ c,
                            uint4* __restrict__ oa, uint4* __restrict__ ob,
                            uint4* __restrict__ oc, int n4)
{
    const int i = blockIdx.x * 256 + threadIdx.x;
    if (i >= n4) return;
    const float4* s = (blockIdx.y == 0) ? a : (blockIdx.y == 1) ? b : c;
    uint4*        d = (blockIdx.y == 0) ? oa : (blockIdx.y == 1) ? ob : oc;
    float4 v = s[i];
    uint4 o;
    o.x = f2tf32(v.x); o.y = f2tf32(v.y); o.z = f2tf32(v.z); o.w = f2tf32(v.w);
    d[i] = o;
}

__global__ void cvt4_kernel(const float4* __restrict__ a, const float4* __restrict__ b,
                            const float4* __restrict__ c, const float4* __restrict__ e,
                            uint4* __restrict__ oa, uint4* __restrict__ ob,
                            uint4* __restrict__ oc, uint4* __restrict__ oe, int n4)
{
    const int i = blockIdx.x * 256 + threadIdx.x;
    if (i >= n4) return;
    const float4* s = (blockIdx.y == 0) ? a : (blockIdx.y == 1) ? b : (blockIdx.y == 2) ? c : e;
    uint4*        d = (blockIdx.y == 0) ? oa : (blockIdx.y == 1) ? ob : (blockIdx.y == 2) ? oc : oe;
    float4 v = s[i];
    uint4 o;
    o.x = f2tf32(v.x); o.y = f2tf32(v.y); o.z = f2tf32(v.z); o.w = f2tf32(v.w);
    d[i] = o;
}

// ---------------------------------------------------------------------------
// tf32 GEMM: C[M,N] = A[M,K] @ W[K,N] + bias, inputs pre-converted tf32 bits.
// Block 128x128, 128 threads (4 warps), warp tile 64x64, K-tile 32,
// 2-stage cp.async double buffer. Dynamic smem = 70656 B.
// SPLIT_TF32: headsplit output layout + store tf32 bits.
// ---------------------------------------------------------------------------
#define GEMM_SMEM ((2 * 128 * 36 + 2 * 32 * 132) * 4)

template <bool SPLIT_TF32>
__device__ __forceinline__ void gemm_body(
    const uint32_t* __restrict__ A, const uint32_t* __restrict__ W,
    const float* __restrict__ bias, float* __restrict__ out)
{
    extern __shared__ uint32_t dsm[];
    uint32_t (*As)[128][36] = (uint32_t(*)[128][36])dsm;                 // [2][128][36]
    uint32_t (*Bs)[32][132] = (uint32_t(*)[32][132])(dsm + 2 * 128 * 36);

    const int tid  = threadIdx.x;
    const int lane = tid & 31;
    const int warp = tid >> 5;
    const int gid  = lane >> 2;
    const int tig  = lane & 3;
    const int wm   = (warp & 1) * 64;
    const int wn   = (warp >> 1) * 64;
    const int row0 = blockIdx.y * 128;
    const int col0 = blockIdx.x * 128;

    auto issue = [&](int kt, int s) {
#pragma unroll
        for (int it = 0; it < 8; it++) {
            const int c = it * 128 + tid;
            const int r = c >> 3, u = (c & 7) * 4;
            cp16(&As[s][r][u], A + (size_t)(row0 + r) * Dv + kt * 32 + u);
        }
#pragma unroll
        for (int it = 0; it < 8; it++) {
            const int c = it * 128 + tid;
            const int r = c >> 5, u = (c & 31) * 4;
            cp16(&Bs[s][r][u], W + (size_t)(kt * 32 + r) * Dv + col0 + u);
        }
    };

    float acc[4][8][4] = {};

    issue(0, 0); CP_COMMIT;
    issue(1, 1); CP_COMMIT;

    const int NT = Dv / 32;  // 24
    for (int kt = 0; kt < NT; kt++) {
        CP_WAIT1;
        __syncthreads();
        const int s = kt & 1;
#pragma unroll
        for (int ks = 0; ks < 4; ks++) {
            uint32_t af[4][4], bf[8][2];
            const int kk = ks * 8 + tig;
#pragma unroll
            for (int mt = 0; mt < 4; mt++) {
                const int m = wm + mt * 16 + gid;
                af[mt][0] = As[s][m][kk];
                af[mt][1] = As[s][m + 8][kk];
                af[mt][2] = As[s][m][kk + 4];
                af[mt][3] = As[s][m + 8][kk + 4];
            }
#pragma unroll
            for (int nt = 0; nt < 8; nt++) {
                const int n = wn + nt * 8 + gid;
                bf[nt][0] = Bs[s][kk][n];
                bf[nt][1] = Bs[s][kk + 4][n];
            }
#pragma unroll
            for (int mt = 0; mt < 4; mt++)
#pragma unroll
                for (int nt = 0; nt < 8; nt++)
                    mma_tf32(acc[mt][nt], af[mt], bf[nt]);
        }
        __syncthreads();
        if (kt + 2 < NT) issue(kt + 2, s);
        CP_COMMIT;
    }

    // epilogue
#pragma unroll
    for (int mt = 0; mt < 4; mt++) {
        const int r0 = row0 + wm + mt * 16 + gid;
        const int r1 = r0 + 8;
#pragma unroll
        for (int nt = 0; nt < 8; nt++) {
            const float* d = acc[mt][nt];
            const int n = col0 + wn + nt * 8 + 2 * tig;
            const float b0 = bias[n];
            const float b1 = bias[n + 1];
            if (SPLIT_TF32) {
                const int hh = n >> 6;
                const int hd = n & 63;
                float2 v0, v1;
                v0.x = __uint_as_float(f2tf32(d[0] + b0));
                v0.y = __uint_as_float(f2tf32(d[1] + b1));
                v1.x = __uint_as_float(f2tf32(d[2] + b0));
                v1.y = __uint_as_float(f2tf32(d[3] + b1));
                {
                    const int bb = r0 >> 11, ss = r0 & 2047;
                    *(float2*)&out[(((size_t)(bb * Hv + hh) * Sv) + ss) * HDv + hd] = v0;
                }
                {
                    const int bb = r1 >> 11, ss = r1 & 2047;
                    *(float2*)&out[(((size_t)(bb * Hv + hh) * Sv) + ss) * HDv + hd] = v1;
                }
            } else {
                *(float2*)&out[(size_t)r0 * Dv + n] = make_float2(d[0] + b0, d[1] + b1);
                *(float2*)&out[(size_t)r1 * Dv + n] = make_float2(d[2] + b0, d[3] + b1);
            }
        }
    }
}

__global__ __launch_bounds__(128) void gemm_qkv_kernel(
    const uint32_t* __restrict__ q, const uint32_t* __restrict__ k, const uint32_t* __restrict__ v,
    const uint32_t* __restrict__ Wq, const uint32_t* __restrict__ Wk, const uint32_t* __restrict__ Wv,
    const float* __restrict__ bq, const float* __restrict__ bk, const float* __restrict__ bv,
    float* __restrict__ qh, float* __restrict__ kh, float* __restrict__ vh)
{
    const int z = blockIdx.z;
    const uint32_t* A    = (z == 0) ? q  : (z == 1) ? k  : v;
    const uint32_t* W    = (z == 0) ? Wq : (z == 1) ? Wk : Wv;
    const float*    bias = (z == 0) ? bq : (z == 1) ? bk : bv;
    float*          out  = (z == 0) ? qh : (z == 1) ? kh : vh;
    gemm_body<true>(A, W, bias, out);
}

__global__ __launch_bounds__(128) void gemm_out_kernel(
    const uint32_t* __restrict__ A, const uint32_t* __restrict__ W,
    const float* __restrict__ bias, float* __restrict__ out)
{
    gemm_body<false>(A, W, bias, out);
}

// ---------------------------------------------------------------------------
// tf32 causal flash attention.
// Grid (16, B*H), 128 threads (4 warps). BM=128 (warp-M 32), BN=32.
// Q fragments in registers; K/V in a 3-stage cp.async ring -> ONE
// __syncthreads per tile, prefetch for jt+2 overlaps full compute of jt.
// Dynamic smem: sK[3][32][68], sV[3][32][76], sP[128][36] = 73728 B.
// ---------------------------------------------------------------------------
#define LOG2E 1.4426950408889634f
#define ATTN_SMEM ((3 * 32 * 68 + 3 * 32 * 76 + 128 * 36) * 4)

__global__ __launch_bounds__(128) void attn_mma_kernel(
    const float* __restrict__ qh, const float* __restrict__ kh,
    const float* __restrict__ vh, float* __restrict__ ctx)
{
    extern __shared__ uint32_t dynsm[];
    uint32_t (*sK)[32][68] = (uint32_t(*)[32][68])dynsm;                     // [3][32][68]
    uint32_t (*sV)[32][76] = (uint32_t(*)[32][76])(dynsm + 3 * 32 * 68);     // [3][32][76]
    uint32_t (*sP)[36]     = (uint32_t(*)[36])(dynsm + 3 * 32 * 68 + 3 * 32 * 76); // [128][36]

    const int tid  = threadIdx.x;
    const int lane = tid & 31;
    const int warp = tid >> 5;
    const int gid  = lane >> 2;
    const int tig  = lane & 3;
    const int wm   = warp * 32;

    const int qt = (gridDim.x - 1) - blockIdx.x;  // long blocks first
    const int bh = blockIdx.y;
    const int b  = bh / Hv;
    const int hd = bh % Hv;

    const float* qb = qh + ((size_t)bh * Sv + qt * 128) * 64;
    const float* kb = kh + (size_t)bh * Sv * 64;
    const float* vb = vh + (size_t)bh * Sv * 64;

    // Q fragments: 8 ksteps x 2 mtiles x 4 regs
    const float SC = 0.125f * LOG2E;
    uint32_t qa[8][2][4];
#pragma unroll
    for (int ks = 0; ks < 8; ks++)
#pragma unroll
        for (int mt = 0; mt < 2; mt++) {
            const int r = wm + mt * 16 + gid;
            qa[ks][mt][0] = f2tf32(qb[r * 64 + ks * 8 + tig] * SC);
            qa[ks][mt][1] = f2tf32(qb[(r + 8) * 64 + ks * 8 + tig] * SC);
            qa[ks][mt][2] = f2tf32(qb[r * 64 + ks * 8 + tig + 4] * SC);
            qa[ks][mt][3] = f2tf32(qb[(r + 8) * 64 + ks * 8 + tig + 4] * SC);
        }

    float m[2][2] = {{-1e30f, -1e30f}, {-1e30f, -1e30f}};
    float l[2][2] = {{0.f, 0.f}, {0.f, 0.f}};
    float o[2][8][4] = {};

    auto issueKV = [&](int jt, int s) {
        const float* kp = kb + (size_t)jt * 32 * 64;
        const float* vp = vb + (size_t)jt * 32 * 64;
#pragma unroll
        for (int it = 0; it < 4; it++) {
            const int c = it * 128 + tid;
            const int r = c >> 4, u = (c & 15) * 4;
            cp16(&sK[s][r][u], kp + r * 64 + u);
            cp16(&sV[s][r][u], vp + r * 64 + u);
        }
    };

    const int ntiles = 4 * qt + 4;
    issueKV(0, 0); CP_COMMIT;
    issueKV(1, 1); CP_COMMIT;

    for (int jt = 0; jt < ntiles; jt++) {
        CP_WAIT1;                 // group for tile jt complete (<=1 pending)
        __syncthreads();          // all warps done with tile jt-1 (stage (jt+2)%3)
        if (jt + 2 < ntiles) issueKV(jt + 2, (jt + 2) % 3);
        CP_COMMIT;                // commit (possibly empty) to keep group count aligned
        const int s = jt % 3;

        if (jt * 32 <= qt * 128 + wm + 31) {  // warp has unmasked rows in this tile
            // ---- QK^T ----
            float sacc[2][4][4] = {};
#pragma unroll
            for (int ks = 0; ks < 8; ks++) {
                const int kk = ks * 8 + tig;
#pragma unroll
                for (int nt = 0; nt < 4; nt++) {
                    uint32_t bf[2];
                    bf[0] = sK[s][nt * 8 + gid][kk];
                    bf[1] = sK[s][nt * 8 + gid][kk + 4];
                    mma_tf32(sacc[0][nt], qa[ks][0], bf);
                    mma_tf32(sacc[1][nt], qa[ks][1], bf);
                }
            }

            // ---- causal mask (diagonal region only) ----
            if (jt >= 4 * qt) {
#pragma unroll
                for (int mt = 0; mt < 2; mt++) {
                    const int ig = qt * 128 + wm + mt * 16 + gid;
#pragma unroll
                    for (int nt = 0; nt < 4; nt++) {
                        const int jg = jt * 32 + nt * 8 + 2 * tig;
                        if (jg > ig)         sacc[mt][nt][0] = -1e30f;
                        if (jg + 1 > ig)     sacc[mt][nt][1] = -1e30f;
                        if (jg > ig + 8)     sacc[mt][nt][2] = -1e30f;
                        if (jg + 1 > ig + 8) sacc[mt][nt][3] = -1e30f;
                    }
                }
            }

            // ---- online softmax (log2 domain) ----
#pragma unroll
            for (int mt = 0; mt < 2; mt++) {
                float mx0 = -1e30f, mx1 = -1e30f;
#pragma unroll
                for (int nt = 0; nt < 4; nt++) {
                    mx0 = fmaxf(mx0, fmaxf(sacc[mt][nt][0], sacc[mt][nt][1]));
                    mx1 = fmaxf(mx1, fmaxf(sacc[mt][nt][2], sacc[mt][nt][3]));
                }
                mx0 = fmaxf(mx0, __shfl_xor_sync(0xffffffffu, mx0, 1));
                mx0 = fmaxf(mx0, __shfl_xor_sync(0xffffffffu, mx0, 2));
                mx1 = fmaxf(mx1, __shfl_xor_sync(0xffffffffu, mx1, 1));
                mx1 = fmaxf(mx1, __shfl_xor_sync(0xffffffffu, mx1, 2));

                const float nm0 = fmaxf(m[mt][0], mx0);
                const float nm1 = fmaxf(m[mt][1], mx1);
                const float a0 = ex2(m[mt][0] - nm0);
                const float a1 = ex2(m[mt][1] - nm1);
                m[mt][0] = nm0; m[mt][1] = nm1;

                const int r = wm + mt * 16 + gid;
                float ps0 = 0.f, ps1 = 0.f;
#pragma unroll
                for (int nt = 0; nt < 4; nt++) {
                    const float p00 = ex2(sacc[mt][nt][0] - nm0);
                    const float p01 = ex2(sacc[mt][nt][1] - nm0);
                    const float p10 = ex2(sacc[mt][nt][2] - nm1);
                    const float p11 = ex2(sacc[mt][nt][3] - nm1);
                    ps0 += p00 + p01;
                    ps1 += p10 + p11;
                    uint2 t;
                    t.x = f2tf32(p00); t.y = f2tf32(p01);
                    *(uint2*)&sP[r][nt * 8 + 2 * tig] = t;
                    t.x = f2tf32(p10); t.y = f2tf32(p11);
                    *(uint2*)&sP[r + 8][nt * 8 + 2 * tig] = t;
                }
                ps0 += __shfl_xor_sync(0xffffffffu, ps0, 1);
                ps0 += __shfl_xor_sync(0xffffffffu, ps0, 2);
                ps1 += __shfl_xor_sync(0xffffffffu, ps1, 1);
                ps1 += __shfl_xor_sync(0xffffffffu, ps1, 2);
                l[mt][0] = l[mt][0] * a0 + ps0;
                l[mt][1] = l[mt][1] * a1 + ps1;

#pragma unroll
                for (int nt = 0; nt < 8; nt++) {
                    o[mt][nt][0] *= a0; o[mt][nt][1] *= a0;
                    o[mt][nt][2] *= a1; o[mt][nt][3] *= a1;
                }
            }
            __syncwarp();

            // ---- P @ V ----
#pragma unroll
            for (int ks = 0; ks < 4; ks++) {
                const int kk = ks * 8 + tig;
                uint32_t pa[2][4];
#pragma unroll
                for (int mt = 0; mt < 2; mt++) {
                    const int r = wm + mt * 16 + gid;
                    pa[mt][0] = sP[r][kk];
                    pa[mt][1] = sP[r + 8][kk];
                    pa[mt][2] = sP[r][kk + 4];
                    pa[mt][3] = sP[r + 8][kk + 4];
                }
#pragma unroll
                for (int nt = 0; nt < 8; nt++) {
                    uint32_t bf[2];
                    bf[0] = sV[s][kk][nt * 8 + gid];
                    bf[1] = sV[s][kk + 4][nt * 8 + gid];
                    mma_tf32(o[0][nt], pa[0], bf);
                    mma_tf32(o[1][nt], pa[1], bf);
                }
            }
        }
    }

    // ---- epilogue: normalize, write ctx as tf32 bits ----
#pragma unroll
    for (int mt = 0; mt < 2; mt++)
#pragma unroll
        for (int hf = 0; hf < 2; hf++) {
            const float il = 1.f / l[mt][hf];
            const int r = qt * 128 + wm + mt * 16 + gid + hf * 8;
            float* ob = ctx + ((size_t)(b * Sv + r)) * Dv + hd * 64;
#pragma unroll
            for (int nt = 0; nt < 8; nt++) {
                uint2 w;
                w.x = f2tf32(o[mt][nt][2 * hf + 0] * il);
                w.y = f2tf32(o[mt][nt][2 * hf + 1] * il);
                *(uint2*)&ob[nt * 8 + 2 * tig] = w;
            }
        }
}

// ---------------------------------------------------------------------------
extern "C" void kernel_launch(void* const* d_in, const int* in_sizes, int n_in,
                              void* d_out, int out_size)
{
    const float* q  = (const float*)d_in[0];
    const float* k  = (const float*)d_in[1];
    const float* v  = (const float*)d_in[2];
    // d_in[3] = mask (causal, implemented directly)
    const float* Wq = (const float*)d_in[4];
    const float* bq = (const float*)d_in[5];
    const float* Wk = (const float*)d_in[6];
    const float* bk = (const float*)d_in[7];
    const float* Wv = (const float*)d_in[8];
    const float* bv = (const float*)d_in[9];
    const float* Wo = (const float*)d_in[10];
    const float* bo = (const float*)d_in[11];
    float* out = (float*)d_out;

    void *p_qh, *p_kh, *p_vh, *p_ctx, *p_qc, *p_kc, *p_vc, *p_wq, *p_wk, *p_wv, *p_wo;
    cudaGetSymbolAddress(&p_qh, g_qh);
    cudaGetSymbolAddress(&p_kh, g_kh);
    cudaGetSymbolAddress(&p_vh, g_vh);
    cudaGetSymbolAddress(&p_ctx, g_ctx);
    cudaGetSymbolAddress(&p_qc, g_qc);
    cudaGetSymbolAddress(&p_kc, g_kc);
    cudaGetSymbolAddress(&p_vc, g_vc);
    cudaGetSymbolAddress(&p_wq, g_Wqc);
    cudaGetSymbolAddress(&p_wk, g_Wkc);
    cudaGetSymbolAddress(&p_wv, g_Wvc);
    cudaGetSymbolAddress(&p_wo, g_Woc);

    cudaFuncSetAttribute(gemm_qkv_kernel, cudaFuncAttributeMaxDynamicSharedMemorySize, GEMM_SMEM);
    cudaFuncSetAttribute(gemm_out_kernel, cudaFuncAttributeMaxDynamicSharedMemorySize, GEMM_SMEM);
    cudaFuncSetAttribute(attn_mma_kernel, cudaFuncAttributeMaxDynamicSharedMemorySize, ATTN_SMEM);

    // pre-convert inputs + weights to tf32 bits
    cvt3_kernel<<<dim3(Mv * Dv / 1024, 3), 256>>>(
        (const float4*)q, (const float4*)k, (const float4*)v,
        (uint4*)p_qc, (uint4*)p_kc, (uint4*)p_vc, Mv * Dv / 4);
    cvt4_kernel<<<dim3(Dv * Dv / 1024, 4), 256>>>(
        (const float4*)Wq, (const float4*)Wk, (const float4*)Wv, (const float4*)Wo,
        (uint4*)p_wq, (uint4*)p_wk, (uint4*)p_wv, (uint4*)p_wo, Dv * Dv / 4);

    dim3 gQKV(Dv / 128, Mv / 128, 3);  // (6, 32, 3)
    gemm_qkv_kernel<<<gQKV, 128, GEMM_SMEM>>>(
        (const uint32_t*)p_qc, (const uint32_t*)p_kc, (const uint32_t*)p_vc,
        (const uint32_t*)p_wq, (const uint32_t*)p_wk, (const uint32_t*)p_wv,
        bq, bk, bv, (float*)p_qh, (float*)p_kh, (float*)p_vh);

    dim3 gAttn(Sv / 128, Bv * Hv);     // (16, 24)
    attn_mma_kernel<<<gAttn, 128, ATTN_SMEM>>>((const float*)p_qh, (const float*)p_kh,
                                               (const float*)p_vh, (float*)p_ctx);

    dim3 gGemm(Dv / 128, Mv / 128);    // (6, 32)
    gemm_out_kernel<<<gGemm, 128, GEMM_SMEM>>>(
        (const uint32_t*)p_ctx, (const uint32_t*)p_wo, bo, out);
}